// round 6
// baseline (speedup 1.0000x reference)
#include <cuda_runtime.h>
#include <math.h>
#include <stdint.h>

#define BN   8
#define TN   16
#define CINC 3
#define HD   64
#define HH   64
#define WWN  64
#define HW   4096

#define TW    32
#define TH    8
#define COT   16          // co per block = 8 copairs
#define CHUNK 4
#define RS32  36          // 16B-aligned rows for LDS.128
#define PATCH32 (10 * RS32)            // 360 floats per channel patch
#define PBUF   (8 * PATCH32)           // 2880 floats per chunk buffer
#define WBUF   (4 * CHUNK * 8 * 9)     // 1152 u64 weights per chunk buffer

typedef unsigned long long u64;

__device__ float g_c[2][BN * HD * HW];

__device__ __forceinline__ void ffma2(u64 &d, u64 a, u64 b) {
    asm("fma.rn.f32x2 %0, %1, %2, %0;" : "+l"(d) : "l"(a), "l"(b));
}
__device__ __forceinline__ u64 pack2(float x, float y) {
    u64 r;
    asm("mov.b64 %0, {%1, %2};" : "=l"(r) : "f"(x), "f"(y));
    return r;
}
__device__ __forceinline__ u64 dup2(float x) {
    u64 r;
    asm("mov.b64 %0, {%1, %1};" : "=l"(r) : "f"(x));
    return r;
}
__device__ __forceinline__ float2 unpack2(u64 v) {
    float2 r;
    asm("mov.b64 {%0, %1}, %2;" : "=f"(r.x), "=f"(r.y) : "l"(v));
    return r;
}
__device__ __forceinline__ float sigmoidf_(float x) {
    return 1.0f / (1.0f + __expf(-x));
}
__device__ __forceinline__ void cp_async4(uint32_t dst, const void *src, uint32_t sz) {
    asm volatile("cp.async.ca.shared.global [%0], [%1], 4, %2;"
                 :: "r"(dst), "l"(src), "r"(sz));
}
__device__ __forceinline__ void cp_commit() {
    asm volatile("cp.async.commit_group;" ::: "memory");
}
__device__ __forceinline__ void cp_wait0() {
    asm volatile("cp.async.wait_group 0;" ::: "memory");
}

// Load 10 pv values of one patch row as 3x float4 and duplicate into u64 lanes.
__device__ __forceinline__ void loadrow(const float *__restrict__ row, u64 pv[10]) {
    float4 a = *(const float4 *)(row);
    float4 b = *(const float4 *)(row + 4);
    float4 c = *(const float4 *)(row + 8);
    pv[0] = dup2(a.x); pv[1] = dup2(a.y); pv[2] = dup2(a.z); pv[3] = dup2(a.w);
    pv[4] = dup2(b.x); pv[5] = dup2(b.y); pv[6] = dup2(b.z); pv[7] = dup2(b.w);
    pv[8] = dup2(c.x); pv[9] = dup2(c.y);
}

// weight smem index: cp contiguous in the low dim -> 1-wavefront LDS.64
__device__ __forceinline__ int widx(int tns, int cc, int kk, int cp) {
    return ((tns * CHUNK + cc) * 9 + kk) * 8 + cp;
}

template <bool FIRST, bool LAST>
__global__ void __launch_bounds__(256, 2)
lstm_step(const float *__restrict__ input, const float *__restrict__ timet,
          const float *__restrict__ Wi, const float *__restrict__ bi,
          const float *__restrict__ Wct, const float *__restrict__ bct,
          const float *__restrict__ Wo, const float *__restrict__ bo,
          const float *__restrict__ Wcs, const float *__restrict__ bcs,
          float *__restrict__ out, float *__restrict__ hlast,
          float *__restrict__ clast, int t) {
    __shared__ __align__(16) float spf[2 * PBUF];   // 23 KB patches
    __shared__ u64 wsmf[2 * WBUF];                  // 18.4 KB weights

    // warp-internal: tx (px-group) x tz (copair). warp index = ty (row).
    const int tx = threadIdx.x;   // 0..3
    const int tz = threadIdx.y;   // 0..7  copair (within warp!)
    const int ty = threadIdx.z;   // 0..7  row (warp id)
    const int tid = tx + 4 * tz + 32 * ty;

    const int tile_x = (blockIdx.x & 1) * TW;
    const int tile_y = (blockIdx.x >> 1) * TH;
    const int co_base = blockIdx.y * COT;
    const int b = blockIdx.z;

    const float *xb  = input + ((size_t)(b * TN + t) * CINC) * HW;
    const float *tmb = timet + ((size_t)(b * TN + t)) * HW;
    float *outb = out + ((size_t)(b * TN + t) * HD) * HW;
    const float *hprev = FIRST ? nullptr
                               : out + ((size_t)(b * TN + t - 1) * HD) * HW;
    const float *cprev = &g_c[t & 1][(size_t)b * HD * HW];
    float *cnext = &g_c[(t & 1) ^ 1][(size_t)b * HD * HW];

    const uint32_t sp_sm = (uint32_t)__cvta_generic_to_shared(spf);

    // acc[tensor: i,ct,o,cs][px]
    u64 acc[4][8];
    {
        const int co0 = co_base + tz * 2;
        u64 v;
        v = pack2(bi[co0],  bi[co0 + 1]);
#pragma unroll
        for (int px = 0; px < 8; px++) acc[0][px] = v;
        v = pack2(bct[co0], bct[co0 + 1]);
#pragma unroll
        for (int px = 0; px < 8; px++) acc[1][px] = v;
        v = pack2(bo[co0],  bo[co0 + 1]);
#pragma unroll
        for (int px = 0; px < 8; px++) acc[2][px] = v;
        v = pack2(bcs[co0], bcs[co0 + 1]);
#pragma unroll
        for (int px = 0; px < 8; px++) acc[3][px] = v;
    }

    // ---- async patch loader: 8 channel patches of chunk j0 into buffer buf ----
    auto load_patches_async = [&](int buf, int j0) {
        const uint32_t dstb = sp_sm + (uint32_t)buf * PBUF * 4;
#pragma unroll
        for (int k = 0; k < 12; k++) {
            int e = tid + k * 256;
            if (e < PBUF) {
                int slot = e / PATCH32, pos = e % PATCH32;
                int r = pos / RS32, c = pos % RS32;
                int gy = tile_y - 1 + r, gx = tile_x - 1 + c;
                bool inb = (c < TW + 2) && ((unsigned)gy < HH) && ((unsigned)gx < WWN);
                const float *pl = (slot < 4)
                                      ? hprev + (size_t)(j0 + slot) * HW
                                      : cprev + (size_t)(j0 + slot - 4) * HW;
                const float *src = pl + (inb ? (gy * WWN + gx) : 0);
                cp_async4(dstb + (uint32_t)e * 4, src, inb ? 4u : 0u);
            }
        }
    };

    // ---- weight stage registers (next chunk) ----
    float wv0[5], wv1[5];
    auto load_wchunk_regs = [&](int j0) {
#pragma unroll
        for (int k = 0; k < 5; k++) {
            int e = tid + k * 256;
            if (e < WBUF) {
                int kk = e % 9, r = e / 9;
                int cp = r % 8, r2 = r / 8;
                int cc = r2 % CHUNK, tns = r2 / CHUNK;
                int co0 = co_base + cp * 2;
                int j = j0 + cc;
                if (tns == 0) {
                    wv0[k] = Wi[((size_t)co0 * 67 + 3 + j) * 9 + kk];
                    wv1[k] = Wi[((size_t)(co0 + 1) * 67 + 3 + j) * 9 + kk];
                } else if (tns == 1) {
                    wv0[k] = Wct[((size_t)co0 * 67 + 3 + j) * 9 + kk];
                    wv1[k] = Wct[((size_t)(co0 + 1) * 67 + 3 + j) * 9 + kk];
                } else if (tns == 2) {
                    wv0[k] = Wo[((size_t)co0 * 68 + 3 + j) * 9 + kk];
                    wv1[k] = Wo[((size_t)(co0 + 1) * 68 + 3 + j) * 9 + kk];
                } else {
                    wv0[k] = Wcs[((size_t)co0 * 64 + j) * 9 + kk];
                    wv1[k] = Wcs[((size_t)(co0 + 1) * 64 + j) * 9 + kk];
                }
            }
        }
    };
    auto store_wchunk = [&](int buf) {
#pragma unroll
        for (int k = 0; k < 5; k++) {
            int e = tid + k * 256;
            if (e < WBUF) {
                int kk = e % 9, r = e / 9;
                int cp = r % 8, r2 = r / 8;
                int cc = r2 % CHUNK, tns = r2 / CHUNK;
                wsmf[buf * WBUF + widx(tns, cc, kk, cp)] = pack2(wv0[k], wv1[k]);
            }
        }
    };

    // ================= stage 0: x(3) + time patches into buffer 1 =================
    {
        const uint32_t dstb = sp_sm + (uint32_t)PBUF * 4;  // buf 1
#pragma unroll
        for (int k = 0; k < 6; k++) {
            int e = tid + k * 256;
            if (e < 4 * PATCH32) {
                int slot = e / PATCH32, pos = e % PATCH32;
                int r = pos / RS32, c = pos % RS32;
                int gy = tile_y - 1 + r, gx = tile_x - 1 + c;
                bool inb = (c < TW + 2) && ((unsigned)gy < HH) && ((unsigned)gx < WWN);
                const float *pl = (slot < 3) ? xb + (size_t)slot * HW : tmb;
                const float *src = pl + (inb ? (gy * WWN + gx) : 0);
                cp_async4(dstb + (uint32_t)e * 4, src, inb ? 4u : 0u);
            }
        }
        cp_commit();
        for (int e = tid; e < 720; e += 256) {
            if (e < 648) {
                int kk = e % 9, r = e / 9;
                int cp = r % 8, r2 = r / 8;
                int ci = r2 % 3, tns = r2 / 3;
                int co0 = co_base + cp * 2;
                float w0, w1;
                if (tns == 0) {
                    w0 = Wi[((size_t)co0 * 67 + ci) * 9 + kk];
                    w1 = Wi[((size_t)(co0 + 1) * 67 + ci) * 9 + kk];
                } else if (tns == 1) {
                    w0 = Wct[((size_t)co0 * 67 + ci) * 9 + kk];
                    w1 = Wct[((size_t)(co0 + 1) * 67 + ci) * 9 + kk];
                } else {
                    w0 = Wo[((size_t)co0 * 68 + ci) * 9 + kk];
                    w1 = Wo[((size_t)(co0 + 1) * 68 + ci) * 9 + kk];
                }
                wsmf[WBUF + widx(tns, ci, kk, cp)] = pack2(w0, w1);
            } else {
                int e2 = e - 648;
                int kk = e2 % 9, cp = e2 / 9;
                int co0 = co_base + cp * 2;
                wsmf[WBUF + widx(3, 0, kk, cp)] =
                    pack2(Wo[((size_t)co0 * 68 + 67) * 9 + kk],
                          Wo[((size_t)(co0 + 1) * 68 + 67) * 9 + kk]);
            }
        }
        cp_wait0();
        __syncthreads();
    }

    // prefetch chunk 0 while computing stage 0
    if (!FIRST) {
        load_patches_async(0, 0);
        cp_commit();
        load_wchunk_regs(0);
    }

    {   // stage-0 compute (reads buffer 1): x0,x1 fused pairwise; x2+time fused
        const float *p1 = spf + PBUF;
        const u64 *wb = wsmf + WBUF;
#pragma unroll
        for (int ky = 0; ky < 3; ky++) {
            u64 pva[10], pvb[10];
            loadrow(p1 + 0 * PATCH32 + (ty + ky) * RS32 + tx * 8, pva);
            loadrow(p1 + 1 * PATCH32 + (ty + ky) * RS32 + tx * 8, pvb);
#pragma unroll
            for (int kx = 0; kx < 3; kx++) {
#pragma unroll
                for (int tns = 0; tns < 3; tns++) {
                    u64 w0 = wb[widx(tns, 0, ky * 3 + kx, tz)];
                    u64 w1 = wb[widx(tns, 1, ky * 3 + kx, tz)];
#pragma unroll
                    for (int px = 0; px < 8; px++) {
                        ffma2(acc[tns][px], pva[kx + px], w0);
                        ffma2(acc[tns][px], pvb[kx + px], w1);
                    }
                }
            }
        }
#pragma unroll
        for (int ky = 0; ky < 3; ky++) {
            u64 pva[10], pvb[10];
            loadrow(p1 + 2 * PATCH32 + (ty + ky) * RS32 + tx * 8, pva);
            loadrow(p1 + 3 * PATCH32 + (ty + ky) * RS32 + tx * 8, pvb);
#pragma unroll
            for (int kx = 0; kx < 3; kx++) {
#pragma unroll
                for (int tns = 0; tns < 3; tns++) {
                    u64 w0 = wb[widx(tns, 2, ky * 3 + kx, tz)];
#pragma unroll
                    for (int px = 0; px < 8; px++)
                        ffma2(acc[tns][px], pva[kx + px], w0);
                }
                u64 wt = wb[widx(3, 0, ky * 3 + kx, tz)];
#pragma unroll
                for (int px = 0; px < 8; px++)
                    ffma2(acc[2][px], pvb[kx + px], wt);   // time -> o gate
            }
        }
    }
    if (!FIRST) {
        cp_wait0();
        store_wchunk(0);
    }
    __syncthreads();

    // ================= pipelined chunk loop (fused h+c, warp-staggered cc) =====
    if (!FIRST) {
        const int phase = ty & 3;   // decorrelate LDS bursts across warps
#pragma unroll 1
        for (int jc = 0; jc < HD / CHUNK; jc++) {
            const int buf = jc & 1;
            if (jc < HD / CHUNK - 1) {
                load_patches_async(buf ^ 1, (jc + 1) * CHUNK);
                cp_commit();
                load_wchunk_regs((jc + 1) * CHUNK);
            }
            const float *pb = spf + buf * PBUF;
            const u64 *wb = wsmf + buf * WBUF;
#pragma unroll
            for (int k = 0; k < CHUNK; k++) {
                const int cc = (k + phase) & 3;
                const float *ph = pb + cc * PATCH32;
                const float *pc = pb + (CHUNK + cc) * PATCH32;
#pragma unroll
                for (int ky = 0; ky < 3; ky++) {
                    u64 pvh[10], pvc[10];
                    loadrow(ph + (ty + ky) * RS32 + tx * 8, pvh);
                    loadrow(pc + (ty + ky) * RS32 + tx * 8, pvc);
#pragma unroll
                    for (int kx = 0; kx < 3; kx++) {
#pragma unroll
                        for (int tns = 0; tns < 3; tns++) {
                            u64 w = wb[widx(tns, cc, ky * 3 + kx, tz)];
#pragma unroll
                            for (int px = 0; px < 8; px++)
                                ffma2(acc[tns][px], pvh[kx + px], w);
                        }
                        u64 wc = wb[widx(3, cc, ky * 3 + kx, tz)];
#pragma unroll
                        for (int px = 0; px < 8; px++)
                            ffma2(acc[3][px], pvc[kx + px], wc);
                    }
                }
            }
            if (jc < HD / CHUNK - 1) {
                cp_wait0();
                store_wchunk(buf ^ 1);
            }
            __syncthreads();
        }
    }

    // ================= epilogue =================
    const int y = tile_y + ty;
    const int x0 = tile_x + tx * 8;
    float tmv[8];
#pragma unroll
    for (int px = 0; px < 8; px++) tmv[px] = tanhf(tmb[y * WWN + x0 + px]);

    float fi[2][8], fq[2][8], fo[2][8], fs[2][8];
#pragma unroll
    for (int px = 0; px < 8; px++) {
        float2 u;
        u = unpack2(acc[0][px]); fi[0][px] = u.x; fi[1][px] = u.y;
        u = unpack2(acc[1][px]); fq[0][px] = u.x; fq[1][px] = u.y;
        u = unpack2(acc[2][px]); fo[0][px] = u.x; fo[1][px] = u.y;
        u = unpack2(acc[3][px]); fs[0][px] = u.x; fs[1][px] = u.y;
    }
#pragma unroll
    for (int half = 0; half < 2; half++) {
        const int co = co_base + tz * 2 + half;
        const size_t pbase = (size_t)co * HW + (size_t)y * WWN + x0;
#pragma unroll
        for (int px = 0; px < 8; px++) {
            float ig = sigmoidf_(fi[half][px]);        // f gate == i gate (ref bug)
            float cS = fs[half][px];
            float cp = FIRST ? 0.0f : cprev[pbase + px];
            float cstar = cp - cS * (1.0f + tmv[px]);  // (c - cS) - cS*tanh(tm)
            float ctl = tanhf(fq[half][px]);
            float cn = ig * (cstar + ctl);
            float og = sigmoidf_(fo[half][px]);
            float hn = og * tanhf(cn);
            outb[pbase + px] = hn;
            cnext[pbase + px] = cn;
            if (LAST && hlast != nullptr) {
                size_t lb = ((size_t)b * HD + co) * HW + (size_t)y * WWN + x0 + px;
                hlast[lb] = hn;
                clast[lb] = cn;
            }
        }
    }
}

extern "C" void kernel_launch(void *const *d_in, const int *in_sizes, int n_in,
                              void *d_out, int out_size) {
    (void)in_sizes; (void)n_in;
    const float *input = (const float *)d_in[0];
    const float *timet = (const float *)d_in[1];
    const float *Wi  = (const float *)d_in[2];
    const float *bi  = (const float *)d_in[3];
    const float *Wct = (const float *)d_in[4];
    const float *bct = (const float *)d_in[5];
    const float *Wo  = (const float *)d_in[6];
    const float *bo  = (const float *)d_in[7];
    const float *Wcs = (const float *)d_in[8];
    const float *bcs = (const float *)d_in[9];
    float *out = (float *)d_out;

    const size_t layer_elems = (size_t)BN * TN * HD * HW;
    const size_t hc = (size_t)BN * HD * HW;
    const bool tail = (size_t)out_size >= layer_elems + 2 * hc;
    float *hlast = tail ? out + layer_elems : nullptr;
    float *clast = tail ? out + layer_elems + hc : nullptr;

    dim3 grid(16, HD / COT, BN);
    dim3 block(4, 8, 8);   // x: px-group, y: copair (in-warp), z: row (= warp)
    for (int t = 0; t < TN; t++) {
        if (t == 0)
            lstm_step<true, false><<<grid, block>>>(input, timet, Wi, bi, Wct, bct,
                                                    Wo, bo, Wcs, bcs, out, nullptr,
                                                    nullptr, t);
        else if (t == TN - 1)
            lstm_step<false, true><<<grid, block>>>(input, timet, Wi, bi, Wct, bct,
                                                    Wo, bo, Wcs, bcs, out, hlast,
                                                    clast, t);
        else
            lstm_step<false, false><<<grid, block>>>(input, timet, Wi, bi, Wct, bct,
                                                     Wo, bo, Wcs, bcs, out, nullptr,
                                                     nullptr, t);
    }
}

// round 7
// speedup vs baseline: 1.2189x; 1.2189x over previous
#include <cuda_runtime.h>
#include <math.h>
#include <stdint.h>

#define BN   8
#define TN   16
#define CINC 3
#define HD   64
#define HH   64
#define WWN  64
#define HW   4096

#define TW    16
#define TH    8
#define COT   16          // co per block = 8 copairs (tz = warp id, warp-uniform weights)
#define CHUNK 4
#define NCH   (HD / CHUNK)             // 16 chunks
#define RS32  20                       // 80B rows (16B-aligned at tx*4 floats)
#define PATCH32 (10 * RS32)            // 200 floats per channel patch
#define PBUF   (8 * PATCH32)           // 1600 floats per chunk buffer
#define SLICE  (PBUF / 4)              // 400
#define WCNT   1152                    // u64 weights per stage

typedef unsigned long long u64;

__device__ float g_c[2][BN * HD * HW];
// packed weights: [co-block][stage 0..16][1152] ; stage 0 = x/time, s>=1 = chunk s-1
__device__ u64 g_w[4][NCH + 1][WCNT];

__device__ __forceinline__ void ffma2(u64 &d, u64 a, u64 b) {
    asm("fma.rn.f32x2 %0, %1, %2, %0;" : "+l"(d) : "l"(a), "l"(b));
}
__device__ __forceinline__ u64 pack2(float x, float y) {
    u64 r;
    asm("mov.b64 %0, {%1, %2};" : "=l"(r) : "f"(x), "f"(y));
    return r;
}
__device__ __forceinline__ u64 dup2(float x) {
    u64 r;
    asm("mov.b64 %0, {%1, %1};" : "=l"(r) : "f"(x));
    return r;
}
__device__ __forceinline__ float2 unpack2(u64 v) {
    float2 r;
    asm("mov.b64 {%0, %1}, %2;" : "=f"(r.x), "=f"(r.y) : "l"(v));
    return r;
}
__device__ __forceinline__ float sigmoidf_(float x) {
    return 1.0f / (1.0f + __expf(-x));
}
__device__ __forceinline__ void cp_async4(uint32_t dst, const void *src, uint32_t sz) {
    asm volatile("cp.async.ca.shared.global [%0], [%1], 4, %2;"
                 :: "r"(dst), "l"(src), "r"(sz));
}
__device__ __forceinline__ void cp_async16(uint32_t dst, const void *src) {
    asm volatile("cp.async.ca.shared.global [%0], [%1], 16;"
                 :: "r"(dst), "l"(src));
}
__device__ __forceinline__ void cp_commit() {
    asm volatile("cp.async.commit_group;" ::: "memory");
}
__device__ __forceinline__ void cp_wait0() {
    asm volatile("cp.async.wait_group 0;" ::: "memory");
}

// weight smem/gmem index: cp contiguous low dim
__device__ __forceinline__ int widx(int tns, int cc, int kk, int cp) {
    return ((tns * CHUNK + cc) * 9 + kk) * 8 + cp;
}

// 6 pv values (4 px + 2 halo) of one patch row: float4 + float2, dup'd to lanes
__device__ __forceinline__ void loadrow6(const float *__restrict__ row, u64 pv[6]) {
    float4 a = *(const float4 *)(row);
    float2 b = *(const float2 *)(row + 4);
    pv[0] = dup2(a.x); pv[1] = dup2(a.y); pv[2] = dup2(a.z);
    pv[3] = dup2(a.w); pv[4] = dup2(b.x); pv[5] = dup2(b.y);
}

// ===================== weight pre-packing kernel (runs once per launch) ======
__global__ void pack_weights(const float *__restrict__ Wi, const float *__restrict__ Wct,
                             const float *__restrict__ Wo, const float *__restrict__ Wcs) {
    int idx = blockIdx.x * 256 + threadIdx.x;
    const int TOT = 4 * (NCH + 1) * WCNT;
    if (idx >= TOT) return;
    int e = idx % WCNT;
    int s = (idx / WCNT) % (NCH + 1);
    int cb = idx / (WCNT * (NCH + 1));
    int cp = e % 8;
    int q = e / 8;
    int kk = q % 9; q /= 9;
    int cc = q % CHUNK;
    int tns = q / CHUNK;
    int co0 = cb * COT + cp * 2;
    float w0 = 0.0f, w1 = 0.0f;
    if (s == 0) {
        if (tns < 3 && cc < 3) {        // x channels
            int ci = cc;
            if (tns == 0) {
                w0 = Wi[((size_t)co0 * 67 + ci) * 9 + kk];
                w1 = Wi[((size_t)(co0 + 1) * 67 + ci) * 9 + kk];
            } else if (tns == 1) {
                w0 = Wct[((size_t)co0 * 67 + ci) * 9 + kk];
                w1 = Wct[((size_t)(co0 + 1) * 67 + ci) * 9 + kk];
            } else {
                w0 = Wo[((size_t)co0 * 68 + ci) * 9 + kk];
                w1 = Wo[((size_t)(co0 + 1) * 68 + ci) * 9 + kk];
            }
        } else if (tns == 3 && cc == 0) {  // time channel -> o gate weights
            w0 = Wo[((size_t)co0 * 68 + 67) * 9 + kk];
            w1 = Wo[((size_t)(co0 + 1) * 68 + 67) * 9 + kk];
        }
    } else {
        int j = (s - 1) * CHUNK + cc;
        if (tns == 0) {
            w0 = Wi[((size_t)co0 * 67 + 3 + j) * 9 + kk];
            w1 = Wi[((size_t)(co0 + 1) * 67 + 3 + j) * 9 + kk];
        } else if (tns == 1) {
            w0 = Wct[((size_t)co0 * 67 + 3 + j) * 9 + kk];
            w1 = Wct[((size_t)(co0 + 1) * 67 + 3 + j) * 9 + kk];
        } else if (tns == 2) {
            w0 = Wo[((size_t)co0 * 68 + 3 + j) * 9 + kk];
            w1 = Wo[((size_t)(co0 + 1) * 68 + 3 + j) * 9 + kk];
        } else {
            w0 = Wcs[((size_t)co0 * 64 + j) * 9 + kk];
            w1 = Wcs[((size_t)(co0 + 1) * 64 + j) * 9 + kk];
        }
    }
    g_w[cb][s][e] = pack2(w0, w1);
}

// ===================== main step kernel ======================================
template <bool FIRST, bool LAST>
__global__ void __launch_bounds__(256, 3)
lstm_step(const float *__restrict__ input, const float *__restrict__ timet,
          const float *__restrict__ bi, const float *__restrict__ bct,
          const float *__restrict__ bo, const float *__restrict__ bcs,
          float *__restrict__ out, float *__restrict__ hlast,
          float *__restrict__ clast, int t) {
    __shared__ __align__(16) float spf[2 * PBUF];   // 12.8 KB patches
    __shared__ __align__(16) u64 wsmf[2 * WCNT];    // 18.4 KB weights

    const int tx = threadIdx.x;   // 0..3  (4-px group)      } warp = tx x ty
    const int ty = threadIdx.y;   // 0..7  (row)             }
    const int tz = threadIdx.z;   // 0..7  copair = warp id (weights warp-uniform)
    const int tid = tx + 4 * ty + 32 * tz;

    const int tile_x = (blockIdx.x & 3) * TW;
    const int tile_y = (blockIdx.x >> 2) * TH;
    const int cb = blockIdx.y;          // co block
    const int co_base = cb * COT;
    const int b = blockIdx.z;

    const float *xb  = input + ((size_t)(b * TN + t) * CINC) * HW;
    const float *tmb = timet + ((size_t)(b * TN + t)) * HW;
    float *outb = out + ((size_t)(b * TN + t) * HD) * HW;
    const float *hprev = FIRST ? nullptr
                               : out + ((size_t)(b * TN + t - 1) * HD) * HW;
    const float *cprev = &g_c[t & 1][(size_t)b * HD * HW];
    float *cnext = &g_c[(t & 1) ^ 1][(size_t)b * HD * HW];

    const uint32_t sp_sm = (uint32_t)__cvta_generic_to_shared(spf);
    const uint32_t w_sm = (uint32_t)__cvta_generic_to_shared(wsmf);

    // acc[tensor: i,ct,o,cs][px 0..3]
    u64 acc[4][4];
    {
        const int co0 = co_base + tz * 2;
        u64 v;
        v = pack2(bi[co0],  bi[co0 + 1]);
#pragma unroll
        for (int px = 0; px < 4; px++) acc[0][px] = v;
        v = pack2(bct[co0], bct[co0 + 1]);
#pragma unroll
        for (int px = 0; px < 4; px++) acc[1][px] = v;
        v = pack2(bo[co0],  bo[co0 + 1]);
#pragma unroll
        for (int px = 0; px < 4; px++) acc[2][px] = v;
        v = pack2(bcs[co0], bcs[co0 + 1]);
#pragma unroll
        for (int px = 0; px < 4; px++) acc[3][px] = v;
    }

    // ---- async weight stage loader: 1152 u64 from g_w[cb][s] into wbuf ----
    auto load_weights_async = [&](int wbuf, int s) {
        const u64 *src = &g_w[cb][s][0];
        const uint32_t dstb = w_sm + (uint32_t)wbuf * WCNT * 8;
#pragma unroll
        for (int k = 0; k < 3; k++) {
            int e = tid + k * 256;      // 16B units, 576 total
            if (e < WCNT / 2)
                cp_async16(dstb + (uint32_t)e * 16, src + (size_t)e * 2);
        }
    };

    // ---- async patch slice loader: quarter s of chunk j0 into buffer buf ----
    auto load_patch_slice = [&](int buf, int j0, int s) {
        const uint32_t dstb = sp_sm + (uint32_t)buf * PBUF * 4;
#pragma unroll
        for (int k = 0; k < 2; k++) {
            int e = s * SLICE + tid + k * 256;
            if (e < (s + 1) * SLICE) {
                int slot = e / PATCH32, pos = e % PATCH32;
                int r = pos / RS32, c = pos % RS32;
                int gy = tile_y - 1 + r, gx = tile_x - 1 + c;
                bool inb = (c < TW + 2) && ((unsigned)gy < HH) && ((unsigned)gx < WWN);
                const float *pl = (slot < 4)
                                      ? hprev + (size_t)(j0 + slot) * HW
                                      : cprev + (size_t)(j0 + slot - 4) * HW;
                cp_async4(dstb + (uint32_t)e * 4, pl + (inb ? (gy * WWN + gx) : 0),
                          inb ? 4u : 0u);
            }
        }
    };

    // ================= stage 0: x(3)+time patches into buf1, weights s=0 =====
    {
        const uint32_t dstb = sp_sm + (uint32_t)PBUF * 4;  // buf 1
#pragma unroll
        for (int k = 0; k < 4; k++) {
            int e = tid + k * 256;
            if (e < 4 * PATCH32) {
                int slot = e / PATCH32, pos = e % PATCH32;
                int r = pos / RS32, c = pos % RS32;
                int gy = tile_y - 1 + r, gx = tile_x - 1 + c;
                bool inb = (c < TW + 2) && ((unsigned)gy < HH) && ((unsigned)gx < WWN);
                const float *pl = (slot < 3) ? xb + (size_t)slot * HW : tmb;
                cp_async4(dstb + (uint32_t)e * 4, pl + (inb ? (gy * WWN + gx) : 0),
                          inb ? 4u : 0u);
            }
        }
        load_weights_async(1, 0);
        cp_commit();
        cp_wait0();
        __syncthreads();
    }

    // prefetch chunk 0 (patches buf0 + weights wbuf0) while computing stage 0
    if (!FIRST) {
        load_weights_async(0, 1);
#pragma unroll
        for (int s = 0; s < 4; s++) load_patch_slice(0, 0, s);
        cp_commit();
    }

    {   // stage-0 compute (reads buf1/wbuf1): x0,x1 fused ; x2+time fused
        const float *p1 = spf + PBUF;
        const u64 *wb = wsmf + WCNT;
#pragma unroll
        for (int ky = 0; ky < 3; ky++) {
            u64 pva[6], pvb[6];
            loadrow6(p1 + 0 * PATCH32 + (ty + ky) * RS32 + tx * 4, pva);
            loadrow6(p1 + 1 * PATCH32 + (ty + ky) * RS32 + tx * 4, pvb);
#pragma unroll
            for (int kx = 0; kx < 3; kx++) {
#pragma unroll
                for (int tns = 0; tns < 3; tns++) {
                    u64 w0 = wb[widx(tns, 0, ky * 3 + kx, tz)];
                    u64 w1 = wb[widx(tns, 1, ky * 3 + kx, tz)];
#pragma unroll
                    for (int px = 0; px < 4; px++) {
                        ffma2(acc[tns][px], pva[kx + px], w0);
                        ffma2(acc[tns][px], pvb[kx + px], w1);
                    }
                }
            }
        }
#pragma unroll
        for (int ky = 0; ky < 3; ky++) {
            u64 pva[6], pvb[6];
            loadrow6(p1 + 2 * PATCH32 + (ty + ky) * RS32 + tx * 4, pva);
            loadrow6(p1 + 3 * PATCH32 + (ty + ky) * RS32 + tx * 4, pvb);
#pragma unroll
            for (int kx = 0; kx < 3; kx++) {
#pragma unroll
                for (int tns = 0; tns < 3; tns++) {
                    u64 w0 = wb[widx(tns, 2, ky * 3 + kx, tz)];
#pragma unroll
                    for (int px = 0; px < 4; px++)
                        ffma2(acc[tns][px], pva[kx + px], w0);
                }
                u64 wt = wb[widx(3, 0, ky * 3 + kx, tz)];
#pragma unroll
                for (int px = 0; px < 4; px++)
                    ffma2(acc[2][px], pvb[kx + px], wt);   // time -> o gate
            }
        }
    }
    if (!FIRST) cp_wait0();
    __syncthreads();

    // ================= pipelined chunk loop =================
    if (!FIRST) {
#pragma unroll 1
        for (int jc = 0; jc < NCH; jc++) {
            const int buf = jc & 1;
            const bool pre = (jc < NCH - 1);
            const float *pb = spf + buf * PBUF;
            const u64 *wb = wsmf + buf * WCNT;
#pragma unroll
            for (int cc = 0; cc < CHUNK; cc++) {
                if (pre) {                       // spread next-chunk loads
                    if (cc == 0) load_weights_async(buf ^ 1, jc + 2);
                    load_patch_slice(buf ^ 1, (jc + 1) * CHUNK, cc);
                    cp_commit();
                }
                const float *ph = pb + cc * PATCH32;
                const float *pc = pb + (CHUNK + cc) * PATCH32;
#pragma unroll
                for (int ky = 0; ky < 3; ky++) {
                    u64 pvh[6], pvc[6];
                    loadrow6(ph + (ty + ky) * RS32 + tx * 4, pvh);
                    loadrow6(pc + (ty + ky) * RS32 + tx * 4, pvc);
#pragma unroll
                    for (int kx = 0; kx < 3; kx++) {
#pragma unroll
                        for (int tns = 0; tns < 3; tns++) {
                            u64 w = wb[widx(tns, cc, ky * 3 + kx, tz)];
#pragma unroll
                            for (int px = 0; px < 4; px++)
                                ffma2(acc[tns][px], pvh[kx + px], w);
                        }
                        u64 wc = wb[widx(3, cc, ky * 3 + kx, tz)];
#pragma unroll
                        for (int px = 0; px < 4; px++)
                            ffma2(acc[3][px], pvc[kx + px], wc);
                    }
                }
            }
            if (pre) cp_wait0();
            __syncthreads();
        }
    }

    // ================= epilogue (vectorized) =================
    const int y = tile_y + ty;
    const int x0 = tile_x + tx * 4;
    float4 tm4 = *(const float4 *)(tmb + y * WWN + x0);
    float tmv[4] = {tanhf(tm4.x), tanhf(tm4.y), tanhf(tm4.z), tanhf(tm4.w)};

    float fi[2][4], fq[2][4], fo[2][4], fs[2][4];
#pragma unroll
    for (int px = 0; px < 4; px++) {
        float2 u;
        u = unpack2(acc[0][px]); fi[0][px] = u.x; fi[1][px] = u.y;
        u = unpack2(acc[1][px]); fq[0][px] = u.x; fq[1][px] = u.y;
        u = unpack2(acc[2][px]); fo[0][px] = u.x; fo[1][px] = u.y;
        u = unpack2(acc[3][px]); fs[0][px] = u.x; fs[1][px] = u.y;
    }
#pragma unroll
    for (int half = 0; half < 2; half++) {
        const int co = co_base + tz * 2 + half;
        const size_t pbase = (size_t)co * HW + (size_t)y * WWN + x0;
        float4 cp4;
        if (FIRST) cp4 = make_float4(0.f, 0.f, 0.f, 0.f);
        else       cp4 = *(const float4 *)(cprev + pbase);
        float cpv[4] = {cp4.x, cp4.y, cp4.z, cp4.w};
        float hn[4], cn[4];
#pragma unroll
        for (int px = 0; px < 4; px++) {
            float ig = sigmoidf_(fi[half][px]);        // f gate == i gate (ref bug)
            float cS = fs[half][px];
            float cstar = cpv[px] - cS * (1.0f + tmv[px]);
            float ctl = tanhf(fq[half][px]);
            cn[px] = ig * (cstar + ctl);
            float og = sigmoidf_(fo[half][px]);
            hn[px] = og * tanhf(cn[px]);
        }
        *(float4 *)(outb + pbase) = make_float4(hn[0], hn[1], hn[2], hn[3]);
        *(float4 *)(cnext + pbase) = make_float4(cn[0], cn[1], cn[2], cn[3]);
        if (LAST && hlast != nullptr) {
            size_t lb = ((size_t)b * HD + co) * HW + (size_t)y * WWN + x0;
            *(float4 *)(hlast + lb) = make_float4(hn[0], hn[1], hn[2], hn[3]);
            *(float4 *)(clast + lb) = make_float4(cn[0], cn[1], cn[2], cn[3]);
        }
    }
}

extern "C" void kernel_launch(void *const *d_in, const int *in_sizes, int n_in,
                              void *d_out, int out_size) {
    (void)in_sizes; (void)n_in;
    const float *input = (const float *)d_in[0];
    const float *timet = (const float *)d_in[1];
    const float *Wi  = (const float *)d_in[2];
    const float *bi  = (const float *)d_in[3];
    const float *Wct = (const float *)d_in[4];
    const float *bct = (const float *)d_in[5];
    const float *Wo  = (const float *)d_in[6];
    const float *bo  = (const float *)d_in[7];
    const float *Wcs = (const float *)d_in[8];
    const float *bcs = (const float *)d_in[9];
    float *out = (float *)d_out;

    const size_t layer_elems = (size_t)BN * TN * HD * HW;
    const size_t hc = (size_t)BN * HD * HW;
    const bool tail = (size_t)out_size >= layer_elems + 2 * hc;
    float *hlast = tail ? out + layer_elems : nullptr;
    float *clast = tail ? out + layer_elems + hc : nullptr;

    {   // pack weights (once per launch; ordered before steps on the stream)
        const int TOT = 4 * (NCH + 1) * WCNT;
        pack_weights<<<(TOT + 255) / 256, 256>>>(Wi, Wct, Wo, Wcs);
    }

    dim3 grid(32, HD / COT, BN);
    dim3 block(4, 8, 8);
    for (int t = 0; t < TN; t++) {
        if (t == 0)
            lstm_step<true, false><<<grid, block>>>(input, timet, bi, bct, bo, bcs,
                                                    out, nullptr, nullptr, t);
        else if (t == TN - 1)
            lstm_step<false, true><<<grid, block>>>(input, timet, bi, bct, bo, bcs,
                                                    out, hlast, clast, t);
        else
            lstm_step<false, false><<<grid, block>>>(input, timet, bi, bct, bo, bcs,
                                                     out, nullptr, nullptr, t);
    }
}

// round 10
// speedup vs baseline: 1.4734x; 1.2087x over previous
#include <cuda_runtime.h>
#include <math.h>
#include <stdint.h>

#define BN   8
#define TN   16
#define CINC 3
#define HD   64
#define HH   64
#define WWN  64
#define HW   4096

#define TW    16
#define TH    8
#define COT   16                       // co per block = 8 copairs
#define CHUNK 4
#define NCH   (HD / CHUNK)             // 16 chunks
#define RS32  20                       // 80B rows
#define PATCH32 (10 * RS32)            // 200 floats per channel patch
#define PBUF   (8 * PATCH32)           // 1600 floats per chunk buffer
#define SLICE  (PBUF / 4)              // 400
#define WCNT   1536                    // u64 weights per stage (4 tns x 4 cc x 8 cp x 3 ky x 4)

typedef unsigned long long u64;

__device__ float g_c[2][BN * HD * HW];
// packed weights: [co-block][stage 0..16][WCNT]; stage 0 = x/time, s>=1 = chunk s-1
__device__ u64 g_w[4][NCH + 1][WCNT];

__device__ __forceinline__ void ffma2(u64 &d, u64 a, u64 b) {
    asm("fma.rn.f32x2 %0, %1, %2, %0;" : "+l"(d) : "l"(a), "l"(b));
}
__device__ __forceinline__ u64 pack2(float x, float y) {
    u64 r;
    asm("mov.b64 %0, {%1, %2};" : "=l"(r) : "f"(x), "f"(y));
    return r;
}
__device__ __forceinline__ u64 dup2(float x) {
    u64 r;
    asm("mov.b64 %0, {%1, %1};" : "=l"(r) : "f"(x));
    return r;
}
__device__ __forceinline__ float2 unpack2(u64 v) {
    float2 r;
    asm("mov.b64 {%0, %1}, %2;" : "=f"(r.x), "=f"(r.y) : "l"(v));
    return r;
}
__device__ __forceinline__ float sigmoidf_(float x) {
    return 1.0f / (1.0f + __expf(-x));
}
__device__ __forceinline__ void cp_async4(uint32_t dst, const void *src, uint32_t sz) {
    asm volatile("cp.async.ca.shared.global [%0], [%1], 4, %2;"
                 :: "r"(dst), "l"(src), "r"(sz));
}
__device__ __forceinline__ void cp_async16(uint32_t dst, const void *src) {
    asm volatile("cp.async.ca.shared.global [%0], [%1], 16;"
                 :: "r"(dst), "l"(src));
}
__device__ __forceinline__ void cp_commit() {
    asm volatile("cp.async.commit_group;" ::: "memory");
}
__device__ __forceinline__ void cp_wait0() {
    asm volatile("cp.async.wait_group 0;" ::: "memory");
}

// weight index: base of the 4-u64 group for (tns, cc, cp, ky); kx in [0,3)
__device__ __forceinline__ int widx(int tns, int cc, int cp, int ky) {
    return (((tns * 4 + cc) * 8 + cp) * 3 + ky) * 4;
}

// 6 pv values (4 px + 2 halo) of one patch row
__device__ __forceinline__ void loadrow6(const float *__restrict__ row, u64 pv[6]) {
    float4 a = *(const float4 *)(row);
    float2 b = *(const float2 *)(row + 4);
    pv[0] = dup2(a.x); pv[1] = dup2(a.y); pv[2] = dup2(a.z);
    pv[3] = dup2(a.w); pv[4] = dup2(b.x); pv[5] = dup2(b.y);
}

// ===================== weight pre-packing kernel =============================
__global__ void pack_weights(const float *__restrict__ Wi, const float *__restrict__ Wct,
                             const float *__restrict__ Wo, const float *__restrict__ Wcs) {
    int idx = blockIdx.x * 256 + threadIdx.x;
    const int TOT = 4 * (NCH + 1) * WCNT;
    if (idx >= TOT) return;
    int e = idx % WCNT;
    int s = (idx / WCNT) % (NCH + 1);
    int cb = idx / (WCNT * (NCH + 1));
    int kx = e & 3;
    int q = e >> 2;
    int ky = q % 3; q /= 3;
    int cp = q % 8; q /= 8;
    int cc = q % 4;
    int tns = q / 4;
    int co0 = cb * COT + cp * 2;
    float w0 = 0.0f, w1 = 0.0f;
    if (kx < 3) {
        int kk = ky * 3 + kx;
        if (s == 0) {
            if (tns < 3 && cc < 3) {           // x channels
                int ci = cc;
                if (tns == 0) {
                    w0 = Wi[((size_t)co0 * 67 + ci) * 9 + kk];
                    w1 = Wi[((size_t)(co0 + 1) * 67 + ci) * 9 + kk];
                } else if (tns == 1) {
                    w0 = Wct[((size_t)co0 * 67 + ci) * 9 + kk];
                    w1 = Wct[((size_t)(co0 + 1) * 67 + ci) * 9 + kk];
                } else {
                    w0 = Wo[((size_t)co0 * 68 + ci) * 9 + kk];
                    w1 = Wo[((size_t)(co0 + 1) * 68 + ci) * 9 + kk];
                }
            } else if (tns == 2 && cc == 3) {  // time channel -> o-gate weights
                w0 = Wo[((size_t)co0 * 68 + 67) * 9 + kk];
                w1 = Wo[((size_t)(co0 + 1) * 68 + 67) * 9 + kk];
            }
        } else {
            int j = (s - 1) * CHUNK + cc;
            if (tns == 0) {
                w0 = Wi[((size_t)co0 * 67 + 3 + j) * 9 + kk];
                w1 = Wi[((size_t)(co0 + 1) * 67 + 3 + j) * 9 + kk];
            } else if (tns == 1) {
                w0 = Wct[((size_t)co0 * 67 + 3 + j) * 9 + kk];
                w1 = Wct[((size_t)(co0 + 1) * 67 + 3 + j) * 9 + kk];
            } else if (tns == 2) {
                w0 = Wo[((size_t)co0 * 68 + 3 + j) * 9 + kk];
                w1 = Wo[((size_t)(co0 + 1) * 68 + 3 + j) * 9 + kk];
            } else {
                w0 = Wcs[((size_t)co0 * 64 + j) * 9 + kk];
                w1 = Wcs[((size_t)(co0 + 1) * 64 + j) * 9 + kk];
            }
        }
    }
    g_w[cb][s][e] = pack2(w0, w1);
}

// ===================== main step kernel ======================================
// Warp specialization: warp w<6 owns tensor tns=w>>1 (i/ct/o) for copairs
// (w&1)*4..+3 and reads ONLY h patches; warps 6,7 own cs for copairs
// (w-6)*4..+3 and read ONLY c patches. Epilogue exchanges acc through smem.
template <bool FIRST, bool LAST>
__global__ void __launch_bounds__(256, 3)
lstm_step(const float *__restrict__ input, const float *__restrict__ timet,
          const float *__restrict__ bi, const float *__restrict__ bct,
          const float *__restrict__ bo, const float *__restrict__ bcs,
          float *__restrict__ out, float *__restrict__ hlast,
          float *__restrict__ clast, int t) {
    // union: [patches 1600 u64][weights 3072 u64] overlaid by exchange (4096 u64)
    __shared__ __align__(16) u64 smem_u[4672];
    float *spf = (float *)smem_u;            // 2 * PBUF floats
    u64 *wsmf = smem_u + 1600;               // 2 * WCNT
    u64 *ex = smem_u;                        // epilogue overlay

    const int tid = threadIdx.x;
    const int w = tid >> 5;
    const int lane = tid & 31;
    const int tx = lane & 3;     // px group
    const int ty = lane >> 2;    // row

    int tnsw, cp0, pslot;
    if (w < 6) { tnsw = w >> 1; cp0 = (w & 1) * 4; pslot = 0; }
    else       { tnsw = 3;      cp0 = (w - 6) * 4; pslot = 4; }

    const int tile_x = (blockIdx.x & 3) * TW;
    const int tile_y = (blockIdx.x >> 2) * TH;
    const int cb = blockIdx.y;
    const int co_base = cb * COT;
    const int b = blockIdx.z;

    const float *xb  = input + ((size_t)(b * TN + t) * CINC) * HW;
    const float *tmb = timet + ((size_t)(b * TN + t)) * HW;
    float *outb = out + ((size_t)(b * TN + t) * HD) * HW;
    const float *hprev = FIRST ? nullptr
                               : out + ((size_t)(b * TN + t - 1) * HD) * HW;
    const float *cprev = &g_c[t & 1][(size_t)b * HD * HW];
    float *cnext = &g_c[(t & 1) ^ 1][(size_t)b * HD * HW];

    const uint32_t sp_sm = (uint32_t)__cvta_generic_to_shared(spf);
    const uint32_t w_sm = (uint32_t)__cvta_generic_to_shared(wsmf);

    // acc[unit 0..3][px 0..3]; unit u = (tnsw, cp0+u)
    u64 acc[4][4];
    {
        const float *bp = (tnsw == 0) ? bi : (tnsw == 1) ? bct
                        : (tnsw == 2) ? bo : bcs;
#pragma unroll
        for (int u = 0; u < 4; u++) {
            int co0 = co_base + (cp0 + u) * 2;
            u64 v = pack2(bp[co0], bp[co0 + 1]);
#pragma unroll
            for (int px = 0; px < 4; px++) acc[u][px] = v;
        }
    }

    auto load_weights_async = [&](int wbuf, int s) {
        const u64 *src = &g_w[cb][s][0];
        const uint32_t dstb = w_sm + (uint32_t)wbuf * WCNT * 8;
#pragma unroll
        for (int k = 0; k < 3; k++) {
            int e = tid + k * 256;              // 768 x 16B
            if (e < WCNT / 2)
                cp_async16(dstb + (uint32_t)e * 16, src + (size_t)e * 2);
        }
    };

    auto load_patch_slice = [&](int buf, int j0, int s) {
        const uint32_t dstb = sp_sm + (uint32_t)buf * PBUF * 4;
#pragma unroll
        for (int k = 0; k < 2; k++) {
            int e = s * SLICE + tid + k * 256;
            if (e < (s + 1) * SLICE) {
                int slot = e / PATCH32, pos = e % PATCH32;
                int r = pos / RS32, c = pos % RS32;
                int gy = tile_y - 1 + r, gx = tile_x - 1 + c;
                bool inb = (c < TW + 2) && ((unsigned)gy < HH) && ((unsigned)gx < WWN);
                const float *pl = (slot < 4)
                                      ? hprev + (size_t)(j0 + slot) * HW
                                      : cprev + (size_t)(j0 + slot - 4) * HW;
                cp_async4(dstb + (uint32_t)e * 4, pl + (inb ? (gy * WWN + gx) : 0),
                          inb ? 4u : 0u);
            }
        }
    };

    // convolve channels [cc0, ccN) of patch block pbase into acc
    auto conv_spec = [&](const float *pbase, const u64 *wb, int cc0, int ccN) {
        for (int cc = cc0; cc < ccN; cc++) {
            const float *pch = pbase + cc * PATCH32;
#pragma unroll
            for (int ky = 0; ky < 3; ky++) {
                u64 pv[6];
                loadrow6(pch + (ty + ky) * RS32 + tx * 4, pv);
#pragma unroll
                for (int u = 0; u < 4; u++) {
                    int base = widx(tnsw, cc, cp0 + u, ky);
                    ulonglong2 w01 = *(const ulonglong2 *)&wb[base];
                    u64 w2 = wb[base + 2];
#pragma unroll
                    for (int px = 0; px < 4; px++) {
                        ffma2(acc[u][px], pv[px], w01.x);
                        ffma2(acc[u][px], pv[px + 1], w01.y);
                        ffma2(acc[u][px], pv[px + 2], w2);
                    }
                }
            }
        }
    };

    // ===== stage 0: x(3)+time patches into buf1, weights s=0 into wbuf1 =====
    {
        const uint32_t dstb = sp_sm + (uint32_t)PBUF * 4;  // buf 1
#pragma unroll
        for (int k = 0; k < 4; k++) {
            int e = tid + k * 256;
            if (e < 4 * PATCH32) {
                int slot = e / PATCH32, pos = e % PATCH32;
                int r = pos / RS32, c = pos % RS32;
                int gy = tile_y - 1 + r, gx = tile_x - 1 + c;
                bool inb = (c < TW + 2) && ((unsigned)gy < HH) && ((unsigned)gx < WWN);
                const float *pl = (slot < 3) ? xb + (size_t)slot * HW : tmb;
                cp_async4(dstb + (uint32_t)e * 4, pl + (inb ? (gy * WWN + gx) : 0),
                          inb ? 4u : 0u);
            }
        }
        load_weights_async(1, 0);
        cp_commit();
        cp_wait0();
        __syncthreads();
    }

    // prefetch chunk 0 while computing stage 0
    if (!FIRST) {
        load_weights_async(0, 1);
#pragma unroll
        for (int s = 0; s < 4; s++) load_patch_slice(0, 0, s);
        cp_commit();
    }

    // stage-0 compute: h-warps only. o-warps also take cc=3 (time channel).
    if (w < 6)
        conv_spec(spf + PBUF, wsmf + WCNT, 0, (tnsw == 2) ? 4 : 3);

    if (!FIRST) cp_wait0();
    __syncthreads();

    // ===== pipelined chunk loop =====
    if (!FIRST) {
#pragma unroll 1
        for (int jc = 0; jc < NCH; jc++) {
            const int buf = jc & 1;
            const bool pre = (jc < NCH - 1);
            const float *pb = spf + buf * PBUF + pslot * PATCH32;
            const u64 *wb = wsmf + buf * WCNT;
            if (pre) {
                load_weights_async(buf ^ 1, jc + 2);
                load_patch_slice(buf ^ 1, (jc + 1) * CHUNK, 0);
                load_patch_slice(buf ^ 1, (jc + 1) * CHUNK, 1);
                cp_commit();
            }
            conv_spec(pb, wb, 0, 2);
            if (pre) {
                load_patch_slice(buf ^ 1, (jc + 1) * CHUNK, 2);
                load_patch_slice(buf ^ 1, (jc + 1) * CHUNK, 3);
                cp_commit();
            }
            conv_spec(pb, wb, 2, 4);
            if (pre) cp_wait0();
            __syncthreads();
        }
    }

    // ===== epilogue: exchange acc across warps, then pointwise update =====
    // write phase: ex[(tns*8+cp)*32 + pos]*4 + px  (pos = ty*4+tx)
#pragma unroll
    for (int u = 0; u < 4; u++) {
        int base = ((tnsw * 8 + cp0 + u) * 32 + (ty * 4 + tx)) * 4;
        *(ulonglong2 *)&ex[base] = make_ulonglong2(acc[u][0], acc[u][1]);
        *(ulonglong2 *)&ex[base + 2] = make_ulonglong2(acc[u][2], acc[u][3]);
    }
    __syncthreads();

    // read phase: copair = warp id, spatial pos = lane
    const int cp = w;
    const int yy = tile_y + (lane >> 2);
    const int xx0 = tile_x + (lane & 3) * 4;

    float f[4][2][4];   // [tns][half][px]
#pragma unroll
    for (int tns = 0; tns < 4; tns++) {
        int base = ((tns * 8 + cp) * 32 + lane) * 4;
        ulonglong2 p0 = *(const ulonglong2 *)&ex[base];
        ulonglong2 p1 = *(const ulonglong2 *)&ex[base + 2];
        float2 u0 = unpack2(p0.x), u1 = unpack2(p0.y);
        float2 u2 = unpack2(p1.x), u3 = unpack2(p1.y);
        f[tns][0][0] = u0.x; f[tns][1][0] = u0.y;
        f[tns][0][1] = u1.x; f[tns][1][1] = u1.y;
        f[tns][0][2] = u2.x; f[tns][1][2] = u2.y;
        f[tns][0][3] = u3.x; f[tns][1][3] = u3.y;
    }

    float4 tm4 = *(const float4 *)(tmb + yy * WWN + xx0);
    float tmv[4] = {tanhf(tm4.x), tanhf(tm4.y), tanhf(tm4.z), tanhf(tm4.w)};

#pragma unroll
    for (int half = 0; half < 2; half++) {
        const int co = co_base + cp * 2 + half;
        const size_t pbase = (size_t)co * HW + (size_t)yy * WWN + xx0;
        float4 cp4;
        if (FIRST) cp4 = make_float4(0.f, 0.f, 0.f, 0.f);
        else       cp4 = *(const float4 *)(cprev + pbase);
        float cpv[4] = {cp4.x, cp4.y, cp4.z, cp4.w};
        float hn[4], cn[4];
#pragma unroll
        for (int px = 0; px < 4; px++) {
            float ig = sigmoidf_(f[0][half][px]);     // f gate == i gate (ref bug)
            float cS = f[3][half][px];
            float cstar = cpv[px] - cS * (1.0f + tmv[px]);
            float ctl = tanhf(f[1][half][px]);
            cn[px] = ig * (cstar + ctl);
            float og = sigmoidf_(f[2][half][px]);
            hn[px] = og * tanhf(cn[px]);
        }
        *(float4 *)(outb + pbase) = make_float4(hn[0], hn[1], hn[2], hn[3]);
        *(float4 *)(cnext + pbase) = make_float4(cn[0], cn[1], cn[2], cn[3]);
        if (LAST && hlast != nullptr) {
            size_t lb = ((size_t)b * HD + co) * HW + (size_t)yy * WWN + xx0;
            *(float4 *)(hlast + lb) = make_float4(hn[0], hn[1], hn[2], hn[3]);
            *(float4 *)(clast + lb) = make_float4(cn[0], cn[1], cn[2], cn[3]);
        }
    }
}

extern "C" void kernel_launch(void *const *d_in, const int *in_sizes, int n_in,
                              void *d_out, int out_size) {
    (void)in_sizes; (void)n_in;
    const float *input = (const float *)d_in[0];
    const float *timet = (const float *)d_in[1];
    const float *Wi  = (const float *)d_in[2];
    const float *bi  = (const float *)d_in[3];
    const float *Wct = (const float *)d_in[4];
    const float *bct = (const float *)d_in[5];
    const float *Wo  = (const float *)d_in[6];
    const float *bo  = (const float *)d_in[7];
    const float *Wcs = (const float *)d_in[8];
    const float *bcs = (const float *)d_in[9];
    float *out = (float *)d_out;

    const size_t layer_elems = (size_t)BN * TN * HD * HW;
    const size_t hc = (size_t)BN * HD * HW;
    const bool tail = (size_t)out_size >= layer_elems + 2 * hc;
    float *hlast = tail ? out + layer_elems : nullptr;
    float *clast = tail ? out + layer_elems + hc : nullptr;

    {   // pack weights once per launch (stream-ordered before the steps)
        const int TOT = 4 * (NCH + 1) * WCNT;
        pack_weights<<<(TOT + 255) / 256, 256>>>(Wi, Wct, Wo, Wcs);
    }

    dim3 grid(32, HD / COT, BN);
    for (int t = 0; t < TN; t++) {
        if (t == 0)
            lstm_step<true, false><<<grid, 256>>>(input, timet, bi, bct, bo, bcs,
                                                  out, nullptr, nullptr, t);
        else if (t == TN - 1)
            lstm_step<false, true><<<grid, 256>>>(input, timet, bi, bct, bo, bcs,
                                                  out, hlast, clast, t);
        else
            lstm_step<false, false><<<grid, 256>>>(input, timet, bi, bct, bo, bcs,
                                                   out, nullptr, nullptr, t);
    }
}

// round 11
// speedup vs baseline: 1.5069x; 1.0228x over previous
#include <cuda_runtime.h>
#include <math.h>
#include <stdint.h>

#define BN   8
#define TN   16
#define CINC 3
#define HD   64
#define HH   64
#define WWN  64
#define HW   4096

#define TW    32
#define TH    8
#define COT   16                       // co per block = 8 copairs
#define CHUNK 4
#define NCH   (HD / CHUNK)             // 16 chunks
#define RS32  36                       // 144B rows, 16B aligned
#define PATCH32 (10 * RS32)            // 360 floats per channel patch
#define PBUF   (8 * PATCH32)           // 2880 floats per chunk buffer
#define SLICE  (PBUF / 4)              // 720
#define WCNT   1536                    // u64 weights per stage (4 tns x 4 cc x 8 cp x 3 ky x 4)

typedef unsigned long long u64;

__device__ float g_c[2][BN * HD * HW];
// packed weights: [co-block][stage 0..16][WCNT]; stage 0 = x/time, s>=1 = chunk s-1
__device__ u64 g_w[4][NCH + 1][WCNT];

__device__ __forceinline__ void ffma2(u64 &d, u64 a, u64 b) {
    asm("fma.rn.f32x2 %0, %1, %2, %0;" : "+l"(d) : "l"(a), "l"(b));
}
__device__ __forceinline__ u64 pack2(float x, float y) {
    u64 r;
    asm("mov.b64 %0, {%1, %2};" : "=l"(r) : "f"(x), "f"(y));
    return r;
}
__device__ __forceinline__ u64 dup2(float x) {
    u64 r;
    asm("mov.b64 %0, {%1, %1};" : "=l"(r) : "f"(x));
    return r;
}
__device__ __forceinline__ float2 unpack2(u64 v) {
    float2 r;
    asm("mov.b64 {%0, %1}, %2;" : "=f"(r.x), "=f"(r.y) : "l"(v));
    return r;
}
__device__ __forceinline__ float sigmoidf_(float x) {
    return 1.0f / (1.0f + __expf(-x));
}
__device__ __forceinline__ void cp_async4(uint32_t dst, const void *src, uint32_t sz) {
    asm volatile("cp.async.ca.shared.global [%0], [%1], 4, %2;"
                 :: "r"(dst), "l"(src), "r"(sz));
}
__device__ __forceinline__ void cp_async16(uint32_t dst, const void *src) {
    asm volatile("cp.async.ca.shared.global [%0], [%1], 16;"
                 :: "r"(dst), "l"(src));
}
__device__ __forceinline__ void cp_commit() {
    asm volatile("cp.async.commit_group;" ::: "memory");
}
__device__ __forceinline__ void cp_wait0() {
    asm volatile("cp.async.wait_group 0;" ::: "memory");
}

// weight index: base of the 4-u64 group for (tns, cc, cp, ky); kx in [0,3)
__device__ __forceinline__ int widx(int tns, int cc, int cp, int ky) {
    return (((tns * 4 + cc) * 8 + cp) * 3 + ky) * 4;
}

// 10 pv values (8 px + 2 halo) of one patch row
__device__ __forceinline__ void loadrow10(const float *__restrict__ row, u64 pv[10]) {
    float4 a = *(const float4 *)(row);
    float4 b = *(const float4 *)(row + 4);
    float2 c = *(const float2 *)(row + 8);
    pv[0] = dup2(a.x); pv[1] = dup2(a.y); pv[2] = dup2(a.z); pv[3] = dup2(a.w);
    pv[4] = dup2(b.x); pv[5] = dup2(b.y); pv[6] = dup2(b.z); pv[7] = dup2(b.w);
    pv[8] = dup2(c.x); pv[9] = dup2(c.y);
}

// ===================== weight pre-packing kernel =============================
__global__ void pack_weights(const float *__restrict__ Wi, const float *__restrict__ Wct,
                             const float *__restrict__ Wo, const float *__restrict__ Wcs) {
    int idx = blockIdx.x * 256 + threadIdx.x;
    const int TOT = 4 * (NCH + 1) * WCNT;
    if (idx >= TOT) return;
    int e = idx % WCNT;
    int s = (idx / WCNT) % (NCH + 1);
    int cb = idx / (WCNT * (NCH + 1));
    int kx = e & 3;
    int q = e >> 2;
    int ky = q % 3; q /= 3;
    int cp = q % 8; q /= 8;
    int cc = q % 4;
    int tns = q / 4;
    int co0 = cb * COT + cp * 2;
    float w0 = 0.0f, w1 = 0.0f;
    if (kx < 3) {
        int kk = ky * 3 + kx;
        if (s == 0) {
            if (tns < 3 && cc < 3) {           // x channels
                int ci = cc;
                if (tns == 0) {
                    w0 = Wi[((size_t)co0 * 67 + ci) * 9 + kk];
                    w1 = Wi[((size_t)(co0 + 1) * 67 + ci) * 9 + kk];
                } else if (tns == 1) {
                    w0 = Wct[((size_t)co0 * 67 + ci) * 9 + kk];
                    w1 = Wct[((size_t)(co0 + 1) * 67 + ci) * 9 + kk];
                } else {
                    w0 = Wo[((size_t)co0 * 68 + ci) * 9 + kk];
                    w1 = Wo[((size_t)(co0 + 1) * 68 + ci) * 9 + kk];
                }
            } else if (tns == 2 && cc == 3) {  // time channel -> o-gate weights
                w0 = Wo[((size_t)co0 * 68 + 67) * 9 + kk];
                w1 = Wo[((size_t)(co0 + 1) * 68 + 67) * 9 + kk];
            }
        } else {
            int j = (s - 1) * CHUNK + cc;
            if (tns == 0) {
                w0 = Wi[((size_t)co0 * 67 + 3 + j) * 9 + kk];
                w1 = Wi[((size_t)(co0 + 1) * 67 + 3 + j) * 9 + kk];
            } else if (tns == 1) {
                w0 = Wct[((size_t)co0 * 67 + 3 + j) * 9 + kk];
                w1 = Wct[((size_t)(co0 + 1) * 67 + 3 + j) * 9 + kk];
            } else if (tns == 2) {
                w0 = Wo[((size_t)co0 * 68 + 3 + j) * 9 + kk];
                w1 = Wo[((size_t)(co0 + 1) * 68 + 3 + j) * 9 + kk];
            } else {
                w0 = Wcs[((size_t)co0 * 64 + j) * 9 + kk];
                w1 = Wcs[((size_t)(co0 + 1) * 64 + j) * 9 + kk];
            }
        }
    }
    g_w[cb][s][e] = pack2(w0, w1);
}

// ===================== main step kernel ======================================
// Tile 32x8, 8 px per thread. Warp specialization: warp w<6 owns tensor
// tns=w>>1 (i/ct/o) for copairs (w&1)*4..+3, reads ONLY h patches; warps 6,7
// own cs, read ONLY c patches. Two-phase epilogue exchange through smem.
template <bool FIRST, bool LAST>
__global__ void __launch_bounds__(256, 2)
lstm_step(const float *__restrict__ input, const float *__restrict__ timet,
          const float *__restrict__ bi, const float *__restrict__ bct,
          const float *__restrict__ bo, const float *__restrict__ bcs,
          float *__restrict__ out, float *__restrict__ hlast,
          float *__restrict__ clast, int t) {
    // union: [patches 2880 u64-equiv][weights 3072 u64]; exchange overlay 4096 u64
    __shared__ __align__(16) u64 smem_u[5952];      // 46.5 KB
    float *spf = (float *)smem_u;                   // 2 * PBUF floats (5760)
    u64 *wsmf = smem_u + 2880;                      // 2 * WCNT
    u64 *ex = smem_u;                               // epilogue overlay (per phase 4096)

    const int tid = threadIdx.x;
    const int w = tid >> 5;
    const int lane = tid & 31;
    const int tx = lane & 3;     // 8-px group
    const int ty = lane >> 2;    // row

    int tnsw, cp0, pslot;
    if (w < 6) { tnsw = w >> 1; cp0 = (w & 1) * 4; pslot = 0; }
    else       { tnsw = 3;      cp0 = (w - 6) * 4; pslot = 4; }

    const int tile_x = (blockIdx.x & 1) * TW;
    const int tile_y = (blockIdx.x >> 1) * TH;
    const int cb = blockIdx.y;
    const int co_base = cb * COT;
    const int b = blockIdx.z;

    const float *xb  = input + ((size_t)(b * TN + t) * CINC) * HW;
    const float *tmb = timet + ((size_t)(b * TN + t)) * HW;
    float *outb = out + ((size_t)(b * TN + t) * HD) * HW;
    const float *hprev = FIRST ? nullptr
                               : out + ((size_t)(b * TN + t - 1) * HD) * HW;
    const float *cprev = &g_c[t & 1][(size_t)b * HD * HW];
    float *cnext = &g_c[(t & 1) ^ 1][(size_t)b * HD * HW];

    const uint32_t sp_sm = (uint32_t)__cvta_generic_to_shared(spf);
    const uint32_t w_sm = (uint32_t)__cvta_generic_to_shared(wsmf);

    // acc[unit 0..3][px 0..7]; unit u = (tnsw, cp0+u)
    u64 acc[4][8];
    {
        const float *bp = (tnsw == 0) ? bi : (tnsw == 1) ? bct
                        : (tnsw == 2) ? bo : bcs;
#pragma unroll
        for (int u = 0; u < 4; u++) {
            int co0 = co_base + (cp0 + u) * 2;
            u64 v = pack2(bp[co0], bp[co0 + 1]);
#pragma unroll
            for (int px = 0; px < 8; px++) acc[u][px] = v;
        }
    }

    auto load_weights_async = [&](int wbuf, int s) {
        const u64 *src = &g_w[cb][s][0];
        const uint32_t dstb = w_sm + (uint32_t)wbuf * WCNT * 8;
#pragma unroll
        for (int k = 0; k < 3; k++) {
            int e = tid + k * 256;              // 768 x 16B
            if (e < WCNT / 2)
                cp_async16(dstb + (uint32_t)e * 16, src + (size_t)e * 2);
        }
    };

    auto load_patch_slice = [&](int buf, int j0, int s) {
        const uint32_t dstb = sp_sm + (uint32_t)buf * PBUF * 4;
#pragma unroll
        for (int k = 0; k < 3; k++) {
            int e = s * SLICE + tid + k * 256;
            if (e < (s + 1) * SLICE) {
                int slot = e / PATCH32, pos = e % PATCH32;
                int r = pos / RS32, c = pos % RS32;
                int gy = tile_y - 1 + r, gx = tile_x - 1 + c;
                bool inb = (c < TW + 2) && ((unsigned)gy < HH) && ((unsigned)gx < WWN);
                const float *pl = (slot < 4)
                                      ? hprev + (size_t)(j0 + slot) * HW
                                      : cprev + (size_t)(j0 + slot - 4) * HW;
                cp_async4(dstb + (uint32_t)e * 4, pl + (inb ? (gy * WWN + gx) : 0),
                          inb ? 4u : 0u);
            }
        }
    };

    // convolve channels [cc0, ccN) of patch block pbase into acc
    auto conv_spec = [&](const float *pbase, const u64 *wb, int cc0, int ccN) {
        for (int cc = cc0; cc < ccN; cc++) {
            const float *pch = pbase + cc * PATCH32;
#pragma unroll
            for (int ky = 0; ky < 3; ky++) {
                u64 pv[10];
                loadrow10(pch + (ty + ky) * RS32 + tx * 8, pv);
#pragma unroll
                for (int u = 0; u < 4; u++) {
                    int base = widx(tnsw, cc, cp0 + u, ky);
                    ulonglong2 w01 = *(const ulonglong2 *)&wb[base];
                    u64 w2 = wb[base + 2];
#pragma unroll
                    for (int px = 0; px < 8; px++) {
                        ffma2(acc[u][px], pv[px], w01.x);
                        ffma2(acc[u][px], pv[px + 1], w01.y);
                        ffma2(acc[u][px], pv[px + 2], w2);
                    }
                }
            }
        }
    };

    // ===== stage 0: x(3)+time patches into buf1, weights s=0 into wbuf1 =====
    {
        const uint32_t dstb = sp_sm + (uint32_t)PBUF * 4;  // buf 1
#pragma unroll
        for (int k = 0; k < 6; k++) {
            int e = tid + k * 256;
            if (e < 4 * PATCH32) {
                int slot = e / PATCH32, pos = e % PATCH32;
                int r = pos / RS32, c = pos % RS32;
                int gy = tile_y - 1 + r, gx = tile_x - 1 + c;
                bool inb = (c < TW + 2) && ((unsigned)gy < HH) && ((unsigned)gx < WWN);
                const float *pl = (slot < 3) ? xb + (size_t)slot * HW : tmb;
                cp_async4(dstb + (uint32_t)e * 4, pl + (inb ? (gy * WWN + gx) : 0),
                          inb ? 4u : 0u);
            }
        }
        load_weights_async(1, 0);
        cp_commit();
        cp_wait0();
        __syncthreads();
    }

    // prefetch chunk 0 while computing stage 0
    if (!FIRST) {
        load_weights_async(0, 1);
#pragma unroll
        for (int s = 0; s < 4; s++) load_patch_slice(0, 0, s);
        cp_commit();
    }

    // stage-0 compute: h-warps only. o-warps also take cc=3 (time channel).
    if (w < 6)
        conv_spec(spf + PBUF, wsmf + WCNT, 0, (tnsw == 2) ? 4 : 3);

    if (!FIRST) cp_wait0();
    __syncthreads();

    // ===== pipelined chunk loop =====
    if (!FIRST) {
#pragma unroll 1
        for (int jc = 0; jc < NCH; jc++) {
            const int buf = jc & 1;
            const bool pre = (jc < NCH - 1);
            const float *pb = spf + buf * PBUF + pslot * PATCH32;
            const u64 *wb = wsmf + buf * WCNT;
            if (pre) {
                load_weights_async(buf ^ 1, jc + 2);
                load_patch_slice(buf ^ 1, (jc + 1) * CHUNK, 0);
                load_patch_slice(buf ^ 1, (jc + 1) * CHUNK, 1);
                cp_commit();
            }
            conv_spec(pb, wb, 0, 2);
            if (pre) {
                load_patch_slice(buf ^ 1, (jc + 1) * CHUNK, 2);
                load_patch_slice(buf ^ 1, (jc + 1) * CHUNK, 3);
                cp_commit();
            }
            conv_spec(pb, wb, 2, 4);
            if (pre) cp_wait0();
            __syncthreads();
        }
    }

    // ===== epilogue: two-phase acc exchange, then pointwise update =====
    // pos = ty*32 + tx*8 + px ; phase A: tensors i(0), ct(1); phase B: o, cs.
    const int pos0w = ty * TW + tx * 8;        // writer base position
    const int cp = w;                          // reader copair
    const int pos0r = (lane >> 2) * TW + (lane & 3) * 8;

    u64 fa[2][8], fb[2][8];
    // phase A write: warps 0..3 (tnsw 0,1)
    if (tnsw < 2) {
#pragma unroll
        for (int u = 0; u < 4; u++) {
            int base = (tnsw * 8 + cp0 + u) * 256 + pos0w;
#pragma unroll
            for (int q = 0; q < 4; q++)
                *(ulonglong2 *)&ex[base + q * 2] =
                    make_ulonglong2(acc[u][q * 2], acc[u][q * 2 + 1]);
        }
    }
    __syncthreads();
#pragma unroll
    for (int tn = 0; tn < 2; tn++) {
        int base = (tn * 8 + cp) * 256 + pos0r;
#pragma unroll
        for (int q = 0; q < 4; q++) {
            ulonglong2 p = *(const ulonglong2 *)&ex[base + q * 2];
            fa[tn][q * 2] = p.x; fa[tn][q * 2 + 1] = p.y;
        }
    }
    __syncthreads();
    // phase B write: warps 4..7 (tnsw 2,3)
    if (tnsw >= 2) {
#pragma unroll
        for (int u = 0; u < 4; u++) {
            int base = ((tnsw - 2) * 8 + cp0 + u) * 256 + pos0w;
#pragma unroll
            for (int q = 0; q < 4; q++)
                *(ulonglong2 *)&ex[base + q * 2] =
                    make_ulonglong2(acc[u][q * 2], acc[u][q * 2 + 1]);
        }
    }
    __syncthreads();
#pragma unroll
    for (int tn = 0; tn < 2; tn++) {
        int base = (tn * 8 + cp) * 256 + pos0r;
#pragma unroll
        for (int q = 0; q < 4; q++) {
            ulonglong2 p = *(const ulonglong2 *)&ex[base + q * 2];
            fb[tn][q * 2] = p.x; fb[tn][q * 2 + 1] = p.y;
        }
    }

    const int yy = tile_y + (lane >> 2);
    const int xx0 = tile_x + (lane & 3) * 8;
    float tmv[8];
    {
        float4 t0 = *(const float4 *)(tmb + yy * WWN + xx0);
        float4 t1 = *(const float4 *)(tmb + yy * WWN + xx0 + 4);
        tmv[0] = tanhf(t0.x); tmv[1] = tanhf(t0.y); tmv[2] = tanhf(t0.z);
        tmv[3] = tanhf(t0.w); tmv[4] = tanhf(t1.x); tmv[5] = tanhf(t1.y);
        tmv[6] = tanhf(t1.z); tmv[7] = tanhf(t1.w);
    }

#pragma unroll
    for (int half = 0; half < 2; half++) {
        const int co = co_base + cp * 2 + half;
        const size_t pbase = (size_t)co * HW + (size_t)yy * WWN + xx0;
        float cpv[8];
        if (FIRST) {
#pragma unroll
            for (int px = 0; px < 8; px++) cpv[px] = 0.0f;
        } else {
            float4 c0 = *(const float4 *)(cprev + pbase);
            float4 c1 = *(const float4 *)(cprev + pbase + 4);
            cpv[0] = c0.x; cpv[1] = c0.y; cpv[2] = c0.z; cpv[3] = c0.w;
            cpv[4] = c1.x; cpv[5] = c1.y; cpv[6] = c1.z; cpv[7] = c1.w;
        }
        float hn[8], cn[8];
#pragma unroll
        for (int px = 0; px < 8; px++) {
            float2 vi = unpack2(fa[0][px]);
            float2 vq = unpack2(fa[1][px]);
            float2 vo = unpack2(fb[0][px]);
            float2 vs = unpack2(fb[1][px]);
            float gi = half ? vi.y : vi.x;
            float gq = half ? vq.y : vq.x;
            float go = half ? vo.y : vo.x;
            float gs = half ? vs.y : vs.x;
            float ig = sigmoidf_(gi);             // f gate == i gate (ref bug)
            float cstar = cpv[px] - gs * (1.0f + tmv[px]);
            float ctl = tanhf(gq);
            cn[px] = ig * (cstar + ctl);
            float og = sigmoidf_(go);
            hn[px] = og * tanhf(cn[px]);
        }
        *(float4 *)(outb + pbase) = make_float4(hn[0], hn[1], hn[2], hn[3]);
        *(float4 *)(outb + pbase + 4) = make_float4(hn[4], hn[5], hn[6], hn[7]);
        *(float4 *)(cnext + pbase) = make_float4(cn[0], cn[1], cn[2], cn[3]);
        *(float4 *)(cnext + pbase + 4) = make_float4(cn[4], cn[5], cn[6], cn[7]);
        if (LAST && hlast != nullptr) {
            size_t lb = ((size_t)b * HD + co) * HW + (size_t)yy * WWN + xx0;
            *(float4 *)(hlast + lb) = make_float4(hn[0], hn[1], hn[2], hn[3]);
            *(float4 *)(hlast + lb + 4) = make_float4(hn[4], hn[5], hn[6], hn[7]);
            *(float4 *)(clast + lb) = make_float4(cn[0], cn[1], cn[2], cn[3]);
            *(float4 *)(clast + lb + 4) = make_float4(cn[4], cn[5], cn[6], cn[7]);
        }
    }
}

extern "C" void kernel_launch(void *const *d_in, const int *in_sizes, int n_in,
                              void *d_out, int out_size) {
    (void)in_sizes; (void)n_in;
    const float *input = (const float *)d_in[0];
    const float *timet = (const float *)d_in[1];
    const float *Wi  = (const float *)d_in[2];
    const float *bi  = (const float *)d_in[3];
    const float *Wct = (const float *)d_in[4];
    const float *bct = (const float *)d_in[5];
    const float *Wo  = (const float *)d_in[6];
    const float *bo  = (const float *)d_in[7];
    const float *Wcs = (const float *)d_in[8];
    const float *bcs = (const float *)d_in[9];
    float *out = (float *)d_out;

    const size_t layer_elems = (size_t)BN * TN * HD * HW;
    const size_t hc = (size_t)BN * HD * HW;
    const bool tail = (size_t)out_size >= layer_elems + 2 * hc;
    float *hlast = tail ? out + layer_elems : nullptr;
    float *clast = tail ? out + layer_elems + hc : nullptr;

    {   // pack weights once per launch (stream-ordered before the steps)
        const int TOT = 4 * (NCH + 1) * WCNT;
        pack_weights<<<(TOT + 255) / 256, 256>>>(Wi, Wct, Wo, Wcs);
    }

    dim3 grid(16, HD / COT, BN);   // 2 x-tiles * 8 y-tiles, 4 co-blocks, 8 batch
    for (int t = 0; t < TN; t++) {
        if (t == 0)
            lstm_step<true, false><<<grid, 256>>>(input, timet, bi, bct, bo, bcs,
                                                  out, nullptr, nullptr, t);
        else if (t == TN - 1)
            lstm_step<false, true><<<grid, 256>>>(input, timet, bi, bct, bo, bcs,
                                                  out, hlast, clast, t);
        else
            lstm_step<false, false><<<grid, 256>>>(input, timet, bi, bct, bo, bcs,
                                                   out, nullptr, nullptr, t);
    }
}